// round 8
// baseline (speedup 1.0000x reference)
#include <cuda_runtime.h>
#include <math.h>

// Shapes
#define B_   32
#define N_   4096
#define C_   128
#define D_   64
#define K_   8
#define H_   128
#define BN_  (B_*N_)          // 131072
#define SLOTS_ (B_*K_)        // 256

// Scratch (device globals; no allocation allowed)
__device__ float g_kT[B_*D_*N_];   // transposed k: [b][d][j]
__device__ float g_v[BN_*D_];
__device__ float g_q[SLOTS_*D_];
__device__ float g_upd[SLOTS_*D_];
__device__ float g_sums[SLOTS_];
__device__ float g_slot[SLOTS_*D_];

// ---- packed f32x2 helpers (Blackwell FFMA2) --------------------------------
__device__ __forceinline__ unsigned long long pack2(float x) {
    unsigned long long r;
    unsigned xi = __float_as_uint(x);
    asm("mov.b64 %0, {%1, %1};" : "=l"(r) : "r"(xi));
    return r;
}
__device__ __forceinline__ unsigned long long packab(float lo, float hi) {
    unsigned long long r;
    asm("mov.b64 %0, {%1, %2};" : "=l"(r)
        : "r"(__float_as_uint(lo)), "r"(__float_as_uint(hi)));
    return r;
}
__device__ __forceinline__ unsigned long long fma2(unsigned long long a,
                                                   unsigned long long b,
                                                   unsigned long long c) {
    unsigned long long d;
    asm("fma.rn.f32x2 %0, %1, %2, %3;" : "=l"(d) : "l"(a), "l"(b), "l"(c));
    return d;
}
__device__ __forceinline__ float2 unpack2(unsigned long long v) {
    unsigned lo, hi;
    asm("mov.b64 {%0, %1}, %2;" : "=r"(lo), "=r"(hi) : "l"(v));
    float2 f;
    f.x = __uint_as_float(lo);
    f.y = __uint_as_float(hi);
    return f;
}

// ---------------------------------------------------------------------------
// Kernel A: x = LN(feat); kT = (x@Wk)^T (via SMEM transpose); v = x@Wv
// ---------------------------------------------------------------------------
__global__ void ln_kv_kernel(const float* __restrict__ feat,
                             const float* __restrict__ gamma,
                             const float* __restrict__ beta,
                             const float* __restrict__ Wk,
                             const float* __restrict__ Wv) {
    extern __shared__ float sm[];
    float* Wc = sm;                 // 128*128
    float* xs = sm + 128*128;       // 64*128 (x tile; reused as k-transpose stage)

    const int tid  = threadIdx.x;
    const int lane = tid & 31;
    const int warp = tid >> 5;

    for (int idx = tid; idx < 128*64; idx += 256) {
        int c = idx >> 6, d = idx & 63;
        Wc[c*128 + d]      = Wk[idx];
        Wc[c*128 + 64 + d] = Wv[idx];
    }
    const float4 gg = ((const float4*)gamma)[lane];
    const float4 bb = ((const float4*)beta)[lane];
    __syncthreads();

    for (int chunk = blockIdx.x; chunk < BN_/64; chunk += gridDim.x) {
        const int row0 = chunk * 64;
        // ---- LN phase ----
        #pragma unroll
        for (int rr = 0; rr < 8; rr++) {
            int rl = warp*8 + rr;
            float4 xv = ((const float4*)(feat + (size_t)(row0+rl)*128))[lane];
            float s  = xv.x+xv.y+xv.z+xv.w;
            float s2 = xv.x*xv.x + xv.y*xv.y + xv.z*xv.z + xv.w*xv.w;
            #pragma unroll
            for (int o = 16; o > 0; o >>= 1) {
                s  += __shfl_xor_sync(0xffffffffu, s,  o);
                s2 += __shfl_xor_sync(0xffffffffu, s2, o);
            }
            float mean = s * (1.f/128.f);
            float var  = s2 * (1.f/128.f) - mean*mean;
            float rstd = rsqrtf(var + 1e-5f);
            float4 xn;
            xn.x = (xv.x-mean)*rstd*gg.x + bb.x;
            xn.y = (xv.y-mean)*rstd*gg.y + bb.y;
            xn.z = (xv.z-mean)*rstd*gg.z + bb.z;
            xn.w = (xv.w-mean)*rstd*gg.w + bb.w;
            ((float4*)(xs + rl*128))[lane] = xn;
        }
        __syncthreads();

        // ---- GEMM: thread = 8 rows x 4 cols (lane<16: k cols, else v) ----
        unsigned long long acc2[8][2];
        #pragma unroll
        for (int ri = 0; ri < 8; ri++) { acc2[ri][0] = 0ULL; acc2[ri][1] = 0ULL; }

        #pragma unroll 2
        for (int c4 = 0; c4 < 32; c4++) {
            float4 xr[8];
            #pragma unroll
            for (int ri = 0; ri < 8; ri++)
                xr[ri] = ((const float4*)(xs + (warp*8+ri)*128))[c4];
            #pragma unroll
            for (int cc = 0; cc < 4; cc++) {
                int c = c4*4 + cc;
                double2 wd = ((const double2*)(Wc + c*128))[lane];
                unsigned long long w01 = __double_as_longlong(wd.x);
                unsigned long long w23 = __double_as_longlong(wd.y);
                #pragma unroll
                for (int ri = 0; ri < 8; ri++) {
                    float xv = (cc == 0) ? xr[ri].x : (cc == 1) ? xr[ri].y
                             : (cc == 2) ? xr[ri].z : xr[ri].w;
                    unsigned long long xx = pack2(xv);
                    acc2[ri][0] = fma2(xx, w01, acc2[ri][0]);
                    acc2[ri][1] = fma2(xx, w23, acc2[ri][1]);
                }
            }
        }
        __syncthreads();   // xs reads complete -> safe to reuse as stage

        // ---- write-back: k -> SMEM transpose stage, v -> direct global ----
        float* kstage = xs;   // 64 d-rows, stride 68
        if (lane < 16) {
            #pragma unroll
            for (int ri = 0; ri < 8; ri++) {
                int jl = warp*8 + ri;
                float2 a0 = unpack2(acc2[ri][0]);
                float2 a1 = unpack2(acc2[ri][1]);
                kstage[(4*lane+0)*68 + jl] = a0.x;
                kstage[(4*lane+1)*68 + jl] = a0.y;
                kstage[(4*lane+2)*68 + jl] = a1.x;
                kstage[(4*lane+3)*68 + jl] = a1.y;
            }
        } else {
            #pragma unroll
            for (int ri = 0; ri < 8; ri++) {
                size_t row = (size_t)(row0 + warp*8 + ri);
                float2 a0 = unpack2(acc2[ri][0]);
                float2 a1 = unpack2(acc2[ri][1]);
                ((float4*)(g_v + row*64))[lane - 16] =
                    make_float4(a0.x, a0.y, a1.x, a1.y);
            }
        }
        __syncthreads();

        // ---- coalesced transposed k store ----
        {
            const size_t bb = (size_t)(row0 >> 12);
            const int jj0 = row0 & 4095;
            for (int idx = tid; idx < 1024; idx += 256) {
                int d = idx >> 4, q = (idx & 15) * 4;
                float4 val = *(const float4*)(kstage + d*68 + q);
                *(float4*)(g_kT + (bb*64 + d)*4096 + jj0 + q) = val;
            }
        }
        __syncthreads();
    }
}

// ---------------------------------------------------------------------------
// Kernel Q: q = LN(slot)@Wq * SCALE; zero accumulators.
// ---------------------------------------------------------------------------
__global__ void q_kernel(const float* __restrict__ slot_src,  // null -> g_slot
                         const float* __restrict__ qg, const float* __restrict__ qb,
                         const float* __restrict__ Wq,
                         const float* __restrict__ qbgg, const float* __restrict__ qbgb,
                         const float* __restrict__ Wqbg) {
    const int r = blockIdx.x;
    const int t = threadIdx.x;
    const bool bg = (r & 7) == 0;
    const float* g = bg ? qbgg : qg;
    const float* bt = bg ? qbgb : qb;
    const float* W = bg ? Wqbg : Wq;
    const float* sp = slot_src ? slot_src : g_slot;

    __shared__ float xn[64];
    __shared__ float ps[2], ps2[2];

    float x = sp[r*64 + t];
    float s = x, s2 = x*x;
    #pragma unroll
    for (int o = 16; o > 0; o >>= 1) {
        s  += __shfl_xor_sync(0xffffffffu, s,  o);
        s2 += __shfl_xor_sync(0xffffffffu, s2, o);
    }
    if ((t & 31) == 0) { ps[t>>5] = s; ps2[t>>5] = s2; }
    __syncthreads();
    s = ps[0] + ps[1]; s2 = ps2[0] + ps2[1];
    float mean = s * (1.f/64.f);
    float var  = s2 * (1.f/64.f) - mean*mean;
    float rstd = rsqrtf(var + 1e-5f);
    xn[t] = (x - mean)*rstd*g[t] + bt[t];
    __syncthreads();

    float a0 = 0.f, a1 = 0.f;
    #pragma unroll 8
    for (int c = 0; c < 64; c += 2) {
        a0 += xn[c]  *__ldg(W + c*64 + t);
        a1 += xn[c+1]*__ldg(W + (c+1)*64 + t);
    }
    g_q[r*64 + t] = (a0 + a1) * 0.125f;   // SCALE folded in

    g_upd[r*64 + t] = 0.f;
    if (t == 0) g_sums[r] = 0.f;
}

// ---------------------------------------------------------------------------
// Kernel ATTN v8: coalesced kT dots + SMEM-staged v for phase 2.
// grid (16, B), 256 threads, one 256-j tile per block.
// Dynamic SMEM: qp (2KB) | vs[256][64] (64KB) | ash[8][256] (8KB)
// ---------------------------------------------------------------------------
__global__ void __launch_bounds__(256)
attn_kernel(float* __restrict__ attn_out) {   // may be null
    extern __shared__ float dynsm[];
    unsigned long long* qp = (unsigned long long*)dynsm;     // [4][64]
    float* vs  = dynsm + 512;                                // [256][64]
    float* ash = vs + 256*64;                                // [8][256]

    const int b  = blockIdx.y;
    const int j0 = blockIdx.x * 256;
    const int t  = threadIdx.x;

    {   // build q pair table (coalesced g_q reads)
        int p = t >> 6, c = t & 63;
        float lo = g_q[b*512 + (2*p)*64 + c];
        float hi = g_q[b*512 + (2*p+1)*64 + c];
        qp[p*64 + c] = packab(lo, hi);
    }

    // ---- stage v tile into SMEM (coalesced float4) ----
    {
        const float4* vsrc = (const float4*)(g_v + (size_t)(b*N_ + j0)*64);
        float4* vdst = (float4*)vs;
        #pragma unroll 4
        for (int idx = t; idx < 4096; idx += 256)
            vdst[idx] = __ldg(vsrc + idx);
    }
    __syncthreads();   // qp visible (vs finishes before the post-softmax barrier)

    // ---- phase 1: thread t owns j = j0 + t; coalesced kT loads ----
    const float* kTb = g_kT + (size_t)(b*64)*4096 + j0 + t;
    unsigned long long dp[4] = {0ULL, 0ULL, 0ULL, 0ULL};
    #pragma unroll 8
    for (int c = 0; c < 64; c++) {
        unsigned long long kc = pack2(__ldg(kTb + (size_t)c*4096));
        dp[0] = fma2(kc, qp[0*64 + c], dp[0]);
        dp[1] = fma2(kc, qp[1*64 + c], dp[1]);
        dp[2] = fma2(kc, qp[2*64 + c], dp[2]);
        dp[3] = fma2(kc, qp[3*64 + c], dp[3]);
    }
    float dots[8];
    #pragma unroll
    for (int p = 0; p < 4; p++) {
        float2 d2 = unpack2(dp[p]);
        dots[2*p]   = d2.x;
        dots[2*p+1] = d2.y;
    }
    float mx = -1e30f;
    #pragma unroll
    for (int i = 0; i < 8; i++) mx = fmaxf(mx, dots[i]);
    float e[8], se = 0.f;
    #pragma unroll
    for (int i = 0; i < 8; i++) { e[i] = __expf(dots[i] - mx); se += e[i]; }
    float inv = 1.f / se;
    #pragma unroll
    for (int i = 0; i < 8; i++) {
        float a = e[i]*inv + 1e-8f;
        ash[i*256 + t] = a;
        if (attn_out)
            attn_out[((size_t)(b*8 + i))*N_ + j0 + t] = a;
    }
    __syncthreads();

    // ---- rowsums ----
    {
        int w = t >> 5, lane = t & 31;
        float s = 0.f;
        #pragma unroll
        for (int q8 = 0; q8 < 8; q8++) s += ash[w*256 + lane + 32*q8];
        #pragma unroll
        for (int o = 16; o > 0; o >>= 1) s += __shfl_xor_sync(0xffffffffu, s, o);
        if (lane == 0) atomicAdd(&g_sums[b*8 + w], s);
    }

    // ---- phase 2: un-normalized attn @ v from SMEM ----
    const int d4    = t & 15;
    const int i8    = (t >> 4) & 7;
    const int jhalf = (t >> 7) * 128;
    float4 up = make_float4(0.f, 0.f, 0.f, 0.f);
    const float* vbase = vs + jhalf*64 + d4*4;
    const float* abase = ash + i8*256 + jhalf;
    #pragma unroll 4
    for (int j = 0; j < 128; j++) {
        float4 vv = *(const float4*)(vbase + j*64);
        float a = abase[j];
        up.x += a*vv.x; up.y += a*vv.y; up.z += a*vv.z; up.w += a*vv.w;
    }
    float* ub = &g_upd[((size_t)(b*8) + i8)*64 + d4*4];
    atomicAdd(ub+0, up.x); atomicAdd(ub+1, up.y);
    atomicAdd(ub+2, up.z); atomicAdd(ub+3, up.w);
}

// ---------------------------------------------------------------------------
// Kernel UPDATE (known-good): one block per batch, 512 threads.
// ---------------------------------------------------------------------------
#define TP_ 65   // padded tile row stride
__global__ void update_kernel(const float* __restrict__ slot_src,  // null -> g_slot
    const float* __restrict__ fg_wih, const float* __restrict__ fg_whh,
    const float* __restrict__ fg_bih, const float* __restrict__ fg_bhh,
    const float* __restrict__ bg_wih, const float* __restrict__ bg_whh,
    const float* __restrict__ bg_bih, const float* __restrict__ bg_bhh,
    const float* __restrict__ fg_lng, const float* __restrict__ fg_lnb,
    const float* __restrict__ fg_w1,  const float* __restrict__ fg_b1,
    const float* __restrict__ fg_w2,  const float* __restrict__ fg_b2,
    const float* __restrict__ bg_lng, const float* __restrict__ bg_lnb,
    const float* __restrict__ bg_w1,  const float* __restrict__ bg_b1,
    const float* __restrict__ bg_w2,  const float* __restrict__ bg_b2,
    float* __restrict__ out_slots) {
    extern __shared__ float dsm[];
    float* s_wih_fg = dsm;                 // 64*TP_
    float* s_whh_fg = s_wih_fg + 64*TP_;
    float* s_wih_bg = s_whh_fg + 64*TP_;
    float* s_whh_bg = s_wih_bg + 64*TP_;

    __shared__ float su[8][64], sh[8][64], sx[8][64], hb[8][128];
    __shared__ float ps[16], ps2[16];

    const int b = blockIdx.x;
    const int t = threadIdx.x;
    const int g = t >> 6;
    const int u = t & 63;
    const int r = b*8 + g;
    const bool bg = (g == 0);
    const float* sp = slot_src ? slot_src : g_slot;

    float inv = 1.f / g_sums[r];
    su[g][u] = g_upd[r*64 + u] * inv;
    float h = sp[r*64 + u];
    sh[g][u] = h;

    const float* bih = bg ? bg_bih : fg_bih;
    const float* bhh = bg ? bg_bhh : fg_bhh;

    float gi[3], gh[3];
    #pragma unroll 1
    for (int p = 0; p < 3; p++) {
        __syncthreads();
        for (int idx = t; idx < 4096; idx += 512) {
            int row = idx >> 6, col = idx & 63;
            int gix = (p*64 + row)*64 + col;
            s_wih_fg[row*TP_ + col] = fg_wih[gix];
            s_whh_fg[row*TP_ + col] = fg_whh[gix];
            s_wih_bg[row*TP_ + col] = bg_wih[gix];
            s_whh_bg[row*TP_ + col] = bg_whh[gix];
        }
        __syncthreads();
        const float* wi = (bg ? s_wih_bg : s_wih_fg) + u*TP_;
        const float* wh = (bg ? s_whh_bg : s_whh_fg) + u*TP_;
        float ai = bih[p*64 + u], ah = bhh[p*64 + u];
        #pragma unroll 8
        for (int c = 0; c < 64; c++) {
            ai += su[g][c]*wi[c];
            ah += sh[g][c]*wh[c];
        }
        gi[p] = ai; gh[p] = ah;
    }

    float rg = 1.f/(1.f + __expf(-(gi[0] + gh[0])));
    float z  = 1.f/(1.f + __expf(-(gi[1] + gh[1])));
    float n  = tanhf(gi[2] + rg*gh[2]);
    float s  = (1.f - z)*n + z*h;

    const float* lng = bg ? bg_lng : fg_lng;
    const float* lnb = bg ? bg_lnb : fg_lnb;
    float a = s, a2 = s*s;
    #pragma unroll
    for (int o = 16; o > 0; o >>= 1) {
        a  += __shfl_xor_sync(0xffffffffu, a,  o);
        a2 += __shfl_xor_sync(0xffffffffu, a2, o);
    }
    int w = t >> 5;
    if ((t & 31) == 0) { ps[w] = a; ps2[w] = a2; }
    __syncthreads();
    a  = ps[g*2]  + ps[g*2+1];
    a2 = ps2[g*2] + ps2[g*2+1];
    float mean = a * (1.f/64.f);
    float var  = a2 * (1.f/64.f) - mean*mean;
    float rstd = rsqrtf(var + 1e-5f);
    sx[g][u] = (s - mean)*rstd*lng[u] + lnb[u];
    __syncthreads();

    const float* w1 = bg ? bg_w1 : fg_w1;
    const float* b1 = bg ? bg_b1 : fg_b1;
    float h0 = b1[u], h1 = b1[u + 64];
    #pragma unroll 8
    for (int c = 0; c < 64; c++) {
        float xc = sx[g][c];
        h0 += xc*__ldg(w1 + c*128 + u);
        h1 += xc*__ldg(w1 + c*128 + u + 64);
    }
    hb[g][u]      = fmaxf(h0, 0.f);
    hb[g][u + 64] = fmaxf(h1, 0.f);
    __syncthreads();

    const float* w2 = bg ? bg_w2 : fg_w2;
    const float* b2 = bg ? bg_b2 : fg_b2;
    float o = s + b2[u];
    #pragma unroll 8
    for (int hh = 0; hh < 128; hh++) o += hb[g][hh]*__ldg(w2 + hh*64 + u);

    g_slot[r*64 + u] = o;
    if (out_slots) out_slots[r*64 + u] = o;
}

// ---------------------------------------------------------------------------
extern "C" void kernel_launch(void* const* d_in, const int* in_sizes, int n_in,
                              void* d_out, int out_size) {
    const float* feat   = (const float*)d_in[0];
    const float* slot   = (const float*)d_in[1];
    const float* nfg    = (const float*)d_in[2];
    const float* nfb    = (const float*)d_in[3];
    const float* Wk     = (const float*)d_in[4];
    const float* Wv     = (const float*)d_in[5];
    const float* qg     = (const float*)d_in[6];
    const float* qb     = (const float*)d_in[7];
    const float* Wq     = (const float*)d_in[8];
    const float* qbgg   = (const float*)d_in[9];
    const float* qbgb   = (const float*)d_in[10];
    const float* Wqbg   = (const float*)d_in[11];
    const float* gwih   = (const float*)d_in[12];
    const float* gwhh   = (const float*)d_in[13];
    const float* gbih   = (const float*)d_in[14];
    const float* gbhh   = (const float*)d_in[15];
    const float* bgwih  = (const float*)d_in[16];
    const float* bgwhh  = (const float*)d_in[17];
    const float* bgbih  = (const float*)d_in[18];
    const float* bgbhh  = (const float*)d_in[19];
    const float* rlng   = (const float*)d_in[20];
    const float* rlnb   = (const float*)d_in[21];
    const float* rw1    = (const float*)d_in[22];
    const float* rb1    = (const float*)d_in[23];
    const float* rw2    = (const float*)d_in[24];
    const float* rb2    = (const float*)d_in[25];
    const float* bglng  = (const float*)d_in[26];
    const float* bglnb  = (const float*)d_in[27];
    const float* bgw1   = (const float*)d_in[28];
    const float* bgb1   = (const float*)d_in[29];
    const float* bgw2   = (const float*)d_in[30];
    const float* bgb2   = (const float*)d_in[31];

    float* out       = (float*)d_out;
    float* out_attn  = out + SLOTS_*D_;   // slots first, then attn

    const int smem_lnkv = (128*128 + 64*128) * (int)sizeof(float);  // 98304 B
    cudaFuncSetAttribute(ln_kv_kernel,
                         cudaFuncAttributeMaxDynamicSharedMemorySize, smem_lnkv);
    const int smem_upd = 4*64*TP_*(int)sizeof(float);  // 66560 B
    cudaFuncSetAttribute(update_kernel,
                         cudaFuncAttributeMaxDynamicSharedMemorySize, smem_upd);
    const int smem_attn = (512 + 256*64 + 8*256) * (int)sizeof(float); // 75776 B
    cudaFuncSetAttribute(attn_kernel,
                         cudaFuncAttributeMaxDynamicSharedMemorySize, smem_attn);

    ln_kv_kernel<<<296, 256, smem_lnkv>>>(feat, nfg, nfb, Wk, Wv);

    for (int it = 0; it < 3; it++) {
        const float* ssrc = (it == 0) ? slot : nullptr;  // null -> g_slot
        q_kernel<<<SLOTS_, 64>>>(ssrc, qg, qb, Wq, qbgg, qbgb, Wqbg);
        attn_kernel<<<dim3(16, B_), 256, smem_attn>>>((it == 2) ? out_attn : nullptr);
        update_kernel<<<B_, 512, smem_upd>>>(ssrc,
            gwih, gwhh, gbih, gbhh,
            bgwih, bgwhh, bgbih, bgbhh,
            rlng, rlnb, rw1, rb1, rw2, rb2,
            bglng, bglnb, bgw1, bgb1, bgw2, bgb2,
            (it == 2) ? out : nullptr);
    }
}

// round 9
// speedup vs baseline: 1.2553x; 1.2553x over previous
#include <cuda_runtime.h>
#include <cooperative_groups.h>
#include <math.h>

namespace cg = cooperative_groups;

// Shapes
#define B_   32
#define N_   4096
#define C_   128
#define D_   64
#define K_   8
#define H_   128
#define BN_  (B_*N_)          // 131072
#define SLOTS_ (B_*K_)        // 256

// Scratch (device globals; no allocation allowed)
__device__ float g_kT[B_*D_*N_];   // transposed k: [b][d][j]
__device__ float g_v[BN_*D_];
__device__ float g_q[SLOTS_*D_];
__device__ float g_upd[SLOTS_*D_];
__device__ float g_sums[SLOTS_];
__device__ float g_slot[SLOTS_*D_];
// Transposed GRU weights: [0]=fg_wih^T [1]=fg_whh^T [2]=bg_wih^T [3]=bg_whh^T
__device__ float g_wT[4][192*64];

// ---- packed f32x2 helpers (Blackwell FFMA2) --------------------------------
__device__ __forceinline__ unsigned long long pack2(float x) {
    unsigned long long r;
    unsigned xi = __float_as_uint(x);
    asm("mov.b64 %0, {%1, %1};" : "=l"(r) : "r"(xi));
    return r;
}
__device__ __forceinline__ unsigned long long packab(float lo, float hi) {
    unsigned long long r;
    asm("mov.b64 %0, {%1, %2};" : "=l"(r)
        : "r"(__float_as_uint(lo)), "r"(__float_as_uint(hi)));
    return r;
}
__device__ __forceinline__ unsigned long long fma2(unsigned long long a,
                                                   unsigned long long b,
                                                   unsigned long long c) {
    unsigned long long d;
    asm("fma.rn.f32x2 %0, %1, %2, %3;" : "=l"(d) : "l"(a), "l"(b), "l"(c));
    return d;
}
__device__ __forceinline__ float2 unpack2(unsigned long long v) {
    unsigned lo, hi;
    asm("mov.b64 {%0, %1}, %2;" : "=r"(lo), "=r"(hi) : "l"(v));
    float2 f;
    f.x = __uint_as_float(lo);
    f.y = __uint_as_float(hi);
    return f;
}

// ---------------------------------------------------------------------------
// Kernel A (known-good R7): x = LN(feat); kT = (x@Wk)^T; v = x@Wv
// ---------------------------------------------------------------------------
__global__ void ln_kv_kernel(const float* __restrict__ feat,
                             const float* __restrict__ gamma,
                             const float* __restrict__ beta,
                             const float* __restrict__ Wk,
                             const float* __restrict__ Wv) {
    extern __shared__ float sm[];
    float* Wc = sm;                 // 128*128
    float* xs = sm + 128*128;       // 64*128

    const int tid  = threadIdx.x;
    const int lane = tid & 31;
    const int warp = tid >> 5;

    for (int idx = tid; idx < 128*64; idx += 256) {
        int c = idx >> 6, d = idx & 63;
        Wc[c*128 + d]      = Wk[idx];
        Wc[c*128 + 64 + d] = Wv[idx];
    }
    const float4 gg = ((const float4*)gamma)[lane];
    const float4 bb = ((const float4*)beta)[lane];
    __syncthreads();

    for (int chunk = blockIdx.x; chunk < BN_/64; chunk += gridDim.x) {
        const int row0 = chunk * 64;
        #pragma unroll
        for (int rr = 0; rr < 8; rr++) {
            int rl = warp*8 + rr;
            float4 xv = ((const float4*)(feat + (size_t)(row0+rl)*128))[lane];
            float s  = xv.x+xv.y+xv.z+xv.w;
            float s2 = xv.x*xv.x + xv.y*xv.y + xv.z*xv.z + xv.w*xv.w;
            #pragma unroll
            for (int o = 16; o > 0; o >>= 1) {
                s  += __shfl_xor_sync(0xffffffffu, s,  o);
                s2 += __shfl_xor_sync(0xffffffffu, s2, o);
            }
            float mean = s * (1.f/128.f);
            float var  = s2 * (1.f/128.f) - mean*mean;
            float rstd = rsqrtf(var + 1e-5f);
            float4 xn;
            xn.x = (xv.x-mean)*rstd*gg.x + bb.x;
            xn.y = (xv.y-mean)*rstd*gg.y + bb.y;
            xn.z = (xv.z-mean)*rstd*gg.z + bb.z;
            xn.w = (xv.w-mean)*rstd*gg.w + bb.w;
            ((float4*)(xs + rl*128))[lane] = xn;
        }
        __syncthreads();

        unsigned long long acc2[8][2];
        #pragma unroll
        for (int ri = 0; ri < 8; ri++) { acc2[ri][0] = 0ULL; acc2[ri][1] = 0ULL; }

        #pragma unroll 2
        for (int c4 = 0; c4 < 32; c4++) {
            float4 xr[8];
            #pragma unroll
            for (int ri = 0; ri < 8; ri++)
                xr[ri] = ((const float4*)(xs + (warp*8+ri)*128))[c4];
            #pragma unroll
            for (int cc = 0; cc < 4; cc++) {
                int c = c4*4 + cc;
                double2 wd = ((const double2*)(Wc + c*128))[lane];
                unsigned long long w01 = __double_as_longlong(wd.x);
                unsigned long long w23 = __double_as_longlong(wd.y);
                #pragma unroll
                for (int ri = 0; ri < 8; ri++) {
                    float xv = (cc == 0) ? xr[ri].x : (cc == 1) ? xr[ri].y
                             : (cc == 2) ? xr[ri].z : xr[ri].w;
                    unsigned long long xx = pack2(xv);
                    acc2[ri][0] = fma2(xx, w01, acc2[ri][0]);
                    acc2[ri][1] = fma2(xx, w23, acc2[ri][1]);
                }
            }
        }
        __syncthreads();

        float* kstage = xs;
        if (lane < 16) {
            #pragma unroll
            for (int ri = 0; ri < 8; ri++) {
                int jl = warp*8 + ri;
                float2 a0 = unpack2(acc2[ri][0]);
                float2 a1 = unpack2(acc2[ri][1]);
                kstage[(4*lane+0)*68 + jl] = a0.x;
                kstage[(4*lane+1)*68 + jl] = a0.y;
                kstage[(4*lane+2)*68 + jl] = a1.x;
                kstage[(4*lane+3)*68 + jl] = a1.y;
            }
        } else {
            #pragma unroll
            for (int ri = 0; ri < 8; ri++) {
                size_t row = (size_t)(row0 + warp*8 + ri);
                float2 a0 = unpack2(acc2[ri][0]);
                float2 a1 = unpack2(acc2[ri][1]);
                ((float4*)(g_v + row*64))[lane - 16] =
                    make_float4(a0.x, a0.y, a1.x, a1.y);
            }
        }
        __syncthreads();

        {
            const size_t bb2 = (size_t)(row0 >> 12);
            const int jj0 = row0 & 4095;
            for (int idx = tid; idx < 1024; idx += 256) {
                int d = idx >> 4, q = (idx & 15) * 4;
                float4 val = *(const float4*)(kstage + d*68 + q);
                *(float4*)(g_kT + (bb2*64 + d)*4096 + jj0 + q) = val;
            }
        }
        __syncthreads();
    }
}

// ---------------------------------------------------------------------------
// FUSED iteration kernel (cooperative): pre-loop (q0 + wT transpose + zero),
// then 3x [grid.sync; attn; grid.sync; update(+fused q)].
// grid = 512 blocks x 256 threads; blocks (b = bid>>4, jb = bid&15) for attn;
// blocks bid<256 own slot-row r=bid for q0/update.
// ---------------------------------------------------------------------------
__global__ void __launch_bounds__(256, 4)
fused_iter_kernel(
    const float* __restrict__ slot,
    const float* __restrict__ qg,   const float* __restrict__ qb,
    const float* __restrict__ Wq,
    const float* __restrict__ qbgg, const float* __restrict__ qbgb,
    const float* __restrict__ Wqbg,
    const float* __restrict__ gwih, const float* __restrict__ gwhh,
    const float* __restrict__ gbih, const float* __restrict__ gbhh,
    const float* __restrict__ bgwih, const float* __restrict__ bgwhh,
    const float* __restrict__ bgbih, const float* __restrict__ bgbhh,
    const float* __restrict__ rlng, const float* __restrict__ rlnb,
    const float* __restrict__ rw1,  const float* __restrict__ rb1,
    const float* __restrict__ rw2,  const float* __restrict__ rb2,
    const float* __restrict__ bglng, const float* __restrict__ bglnb,
    const float* __restrict__ bgw1,  const float* __restrict__ bgb1,
    const float* __restrict__ bgw2,  const float* __restrict__ bgb2,
    float* __restrict__ out_slots,
    float* __restrict__ out_attn) {
    cg::grid_group grid = cg::this_grid();
    const int bid = blockIdx.x;
    const int t   = threadIdx.x;

    __shared__ float ash[8][256];
    __shared__ unsigned long long qp[4][64];
    __shared__ float xn[64];
    __shared__ float ps[4], ps2[4];
    __shared__ float vecs[2][64], ssh[64], gsh[6][64], hb[128], po[2][64];

    // ================= pre-loop =================
    if (bid < 256) {
        const int r = bid;
        const bool bgr = (r & 7) == 0;
        float x = 0.f;
        if (t < 64) {
            x = slot[r*64 + t];
            float s = x, s2 = x*x;
            #pragma unroll
            for (int o = 16; o > 0; o >>= 1) {
                s  += __shfl_xor_sync(0xffffffffu, s,  o);
                s2 += __shfl_xor_sync(0xffffffffu, s2, o);
            }
            if ((t & 31) == 0) { ps[t>>5] = s; ps2[t>>5] = s2; }
        }
        __syncthreads();
        if (t < 64) {
            const float* g  = bgr ? qbgg : qg;
            const float* bt = bgr ? qbgb : qb;
            float s = ps[0] + ps[1], s2 = ps2[0] + ps2[1];
            float mean = s * (1.f/64.f);
            float var  = s2 * (1.f/64.f) - mean*mean;
            float rstd = rsqrtf(var + 1e-5f);
            xn[t] = (x - mean)*rstd*g[t] + bt[t];
        }
        __syncthreads();
        if (t < 64) {
            const float* W = bgr ? Wqbg : Wq;
            float a0 = 0.f, a1 = 0.f;
            #pragma unroll 8
            for (int c = 0; c < 64; c += 2) {
                a0 += xn[c]  *__ldg(W + c*64 + t);
                a1 += xn[c+1]*__ldg(W + (c+1)*64 + t);
            }
            g_q[r*64 + t] = (a0 + a1) * 0.125f;
            g_upd[r*64 + t] = 0.f;
        }
        if (t == 0) g_sums[r] = 0.f;
    } else if (bid < 268) {
        // transpose GRU weights (direct; once)
        const int m = (bid - 256) / 3;
        const int p = (bid - 256) % 3;
        const float* src = (m == 0) ? gwih : (m == 1) ? gwhh
                         : (m == 2) ? bgwih : bgwhh;
        for (int i = t; i < 4096; i += 256) {
            int rr = i >> 6, cc = i & 63;
            g_wT[m][(p*64 + cc)*64 + rr] = src[(p*64 + rr)*64 + cc];
        }
    }

    // ================= iteration loop =================
    for (int it = 0; it < 3; it++) {
        grid.sync();

        // ---------------- attn (all 512 blocks) ----------------
        {
            const int b  = bid >> 4;
            const int j0 = (bid & 15) * 256;
            {
                int p = t >> 6, c = t & 63;
                float lo = g_q[b*512 + (2*p)*64 + c];
                float hi = g_q[b*512 + (2*p+1)*64 + c];
                qp[p][c] = packab(lo, hi);
            }
            __syncthreads();

            const float* kTb = g_kT + (size_t)(b*64)*4096 + j0 + t;
            unsigned long long dp[4] = {0ULL, 0ULL, 0ULL, 0ULL};
            #pragma unroll 8
            for (int c = 0; c < 64; c++) {
                unsigned long long kc = pack2(__ldg(kTb + (size_t)c*4096));
                dp[0] = fma2(kc, qp[0][c], dp[0]);
                dp[1] = fma2(kc, qp[1][c], dp[1]);
                dp[2] = fma2(kc, qp[2][c], dp[2]);
                dp[3] = fma2(kc, qp[3][c], dp[3]);
            }
            float dots[8];
            #pragma unroll
            for (int p = 0; p < 4; p++) {
                float2 d2 = unpack2(dp[p]);
                dots[2*p]   = d2.x;
                dots[2*p+1] = d2.y;
            }
            float mx = -1e30f;
            #pragma unroll
            for (int i = 0; i < 8; i++) mx = fmaxf(mx, dots[i]);
            float e[8], se = 0.f;
            #pragma unroll
            for (int i = 0; i < 8; i++) { e[i] = __expf(dots[i] - mx); se += e[i]; }
            float inv = 1.f / se;
            #pragma unroll
            for (int i = 0; i < 8; i++) {
                float a = e[i]*inv + 1e-8f;
                ash[i][t] = a;
                if (it == 2)
                    out_attn[((size_t)(b*8 + i))*N_ + j0 + t] = a;
            }
            __syncthreads();

            {
                int w = t >> 5, lane = t & 31;
                float s = 0.f;
                #pragma unroll
                for (int q8 = 0; q8 < 8; q8++) s += ash[w][lane + 32*q8];
                #pragma unroll
                for (int o = 16; o > 0; o >>= 1)
                    s += __shfl_xor_sync(0xffffffffu, s, o);
                if (lane == 0) atomicAdd(&g_sums[b*8 + w], s);
            }

            const int d4    = t & 15;
            const int i8    = (t >> 4) & 7;
            const int jhalf = (t >> 7) * 128;
            float4 up = make_float4(0.f, 0.f, 0.f, 0.f);
            const float4* vp = (const float4*)(g_v + ((size_t)b*N_ + j0 + jhalf)*64);
            #pragma unroll 4
            for (int j = 0; j < 128; j++) {
                float4 vv = __ldg(vp + j*16 + d4);
                float a = ash[i8][jhalf + j];
                up.x += a*vv.x; up.y += a*vv.y; up.z += a*vv.z; up.w += a*vv.w;
            }
            float* ub = &g_upd[((size_t)(b*8) + i8)*64 + d4*4];
            atomicAdd(ub+0, up.x); atomicAdd(ub+1, up.y);
            atomicAdd(ub+2, up.z); atomicAdd(ub+3, up.w);
        }

        grid.sync();

        // ---------------- update (blocks 0..255) ----------------
        if (bid < 256) {
            const int r    = bid;
            const int half = t >> 6;      // 0..3
            const int u    = t & 63;
            const bool bgr = (r & 7) == 0;
            const float* sp = (it == 0) ? slot : (const float*)g_slot;

            if (half == 0)      vecs[0][u] = g_upd[r*64 + u] / g_sums[r];
            else if (half == 1) vecs[1][u] = sp[r*64 + u];
            __syncthreads();

            if (half < 2) {
                const float* wT   = (half == 0) ? (bgr ? g_wT[2] : g_wT[0])
                                                : (bgr ? g_wT[3] : g_wT[1]);
                const float* bias = (half == 0) ? (bgr ? bgbih : gbih)
                                                : (bgr ? bgbhh : gbhh);
                const float* vec  = vecs[half];
                #pragma unroll
                for (int p = 0; p < 3; p++) {
                    const float* wp = wT + (size_t)(p*64)*64 + u;
                    float a0 = 0.f, a1 = 0.f, a2 = 0.f, a3 = 0.f;
                    #pragma unroll
                    for (int c = 0; c < 64; c += 4) {
                        a0 += vec[c]  *__ldg(wp + (size_t)(c  )*64);
                        a1 += vec[c+1]*__ldg(wp + (size_t)(c+1)*64);
                        a2 += vec[c+2]*__ldg(wp + (size_t)(c+2)*64);
                        a3 += vec[c+3]*__ldg(wp + (size_t)(c+3)*64);
                    }
                    gsh[half*3 + p][u] = (a0 + a1) + (a2 + a3) + bias[p*64 + u];
                }
            }
            __syncthreads();

            float s = 0.f;
            if (t < 64) {
                float hval = vecs[1][u];
                float rg = 1.f/(1.f + __expf(-(gsh[0][u] + gsh[3][u])));
                float z  = 1.f/(1.f + __expf(-(gsh[1][u] + gsh[4][u])));
                float n  = tanhf(gsh[2][u] + rg*gsh[5][u]);
                s = (1.f - z)*n + z*hval;
                ssh[u] = s;
                float a = s, a2v = s*s;
                #pragma unroll
                for (int o = 16; o > 0; o >>= 1) {
                    a   += __shfl_xor_sync(0xffffffffu, a,   o);
                    a2v += __shfl_xor_sync(0xffffffffu, a2v, o);
                }
                if ((t & 31) == 0) { ps[t>>5] = a; ps2[t>>5] = a2v; }
            }
            __syncthreads();
            if (t < 64) {
                const float* lng = bgr ? bglng : rlng;
                const float* lnb = bgr ? bglnb : rlnb;
                float tot = ps[0] + ps[1], tot2 = ps2[0] + ps2[1];
                float mean = tot * (1.f/64.f);
                float var  = tot2 * (1.f/64.f) - mean*mean;
                float rstd = rsqrtf(var + 1e-5f);
                sx_write: ;
                xn[u] = (s - mean)*rstd*lng[u] + lnb[u];
            }
            __syncthreads();

            if (t < 128) {
                const float* w1 = bgr ? bgw1 : rw1;
                const float* b1 = bgr ? bgb1 : rb1;
                float h0 = b1[t], h1 = 0.f, h2 = 0.f, h3 = 0.f;
                #pragma unroll
                for (int c = 0; c < 64; c += 4) {
                    h0 += xn[c]  *__ldg(w1 + (c  )*128 + t);
                    h1 += xn[c+1]*__ldg(w1 + (c+1)*128 + t);
                    h2 += xn[c+2]*__ldg(w1 + (c+2)*128 + t);
                    h3 += xn[c+3]*__ldg(w1 + (c+3)*128 + t);
                }
                hb[t] = fmaxf((h0 + h1) + (h2 + h3), 0.f);
            }
            __syncthreads();

            if (half < 2) {
                const float* w2 = bgr ? bgw2 : rw2;
                float o0 = 0.f, o1 = 0.f, o2 = 0.f, o3 = 0.f;
                const int hh0 = half * 64;
                #pragma unroll
                for (int hh = 0; hh < 64; hh += 4) {
                    o0 += hb[hh0+hh]  *__ldg(w2 + (hh0+hh  )*64 + u);
                    o1 += hb[hh0+hh+1]*__ldg(w2 + (hh0+hh+1)*64 + u);
                    o2 += hb[hh0+hh+2]*__ldg(w2 + (hh0+hh+2)*64 + u);
                    o3 += hb[hh0+hh+3]*__ldg(w2 + (hh0+hh+3)*64 + u);
                }
                po[half][u] = (o0 + o1) + (o2 + o3);
            }
            __syncthreads();

            float o = 0.f;
            if (t < 64) {
                const float* b2 = bgr ? bgb2 : rb2;
                o = ssh[u] + b2[u] + po[0][u] + po[1][u];
                g_slot[r*64 + u] = o;
                if (it == 2) out_slots[r*64 + u] = o;
            }

            if (it < 2) {
                // fused q for next iteration: LN(o) @ Wq * SCALE
                if (t < 64) {
                    float a = o, a2v = o*o;
                    #pragma unroll
                    for (int off = 16; off > 0; off >>= 1) {
                        a   += __shfl_xor_sync(0xffffffffu, a,   off);
                        a2v += __shfl_xor_sync(0xffffffffu, a2v, off);
                    }
                    if ((t & 31) == 0) { ps[t>>5] = a; ps2[t>>5] = a2v; }
                }
                __syncthreads();
                if (t < 64) {
                    const float* qgp = bgr ? qbgg : qg;
                    const float* qbp = bgr ? qbgb : qb;
                    float tot = ps[0] + ps[1], tot2 = ps2[0] + ps2[1];
                    float mean = tot * (1.f/64.f);
                    float var  = tot2 * (1.f/64.f) - mean*mean;
                    float rstd = rsqrtf(var + 1e-5f);
                    xn[u] = (o - mean)*rstd*qgp[u] + qbp[u];
                }
                __syncthreads();
                if (half < 2) {
                    const float* Wp = bgr ? Wqbg : Wq;
                    const int c0 = half * 32;
                    float q0 = 0.f, q1 = 0.f;
                    #pragma unroll
                    for (int c = 0; c < 32; c += 2) {
                        q0 += xn[c0+c]  *__ldg(Wp + (c0+c  )*64 + u);
                        q1 += xn[c0+c+1]*__ldg(Wp + (c0+c+1)*64 + u);
                    }
                    po[half][u] = q0 + q1;
                }
                __syncthreads();
                if (t < 64) {
                    g_q[r*64 + u] = (po[0][u] + po[1][u]) * 0.125f;
                    g_upd[r*64 + u] = 0.f;
                }
                if (t == 0) g_sums[r] = 0.f;
            }
        }
    }
}

// ---------------------------------------------------------------------------
extern "C" void kernel_launch(void* const* d_in, const int* in_sizes, int n_in,
                              void* d_out, int out_size) {
    const float* feat   = (const float*)d_in[0];
    const float* slot   = (const float*)d_in[1];
    const float* nfg    = (const float*)d_in[2];
    const float* nfb    = (const float*)d_in[3];
    const float* Wk     = (const float*)d_in[4];
    const float* Wv     = (const float*)d_in[5];
    const float* qg     = (const float*)d_in[6];
    const float* qb     = (const float*)d_in[7];
    const float* Wq     = (const float*)d_in[8];
    const float* qbgg   = (const float*)d_in[9];
    const float* qbgb   = (const float*)d_in[10];
    const float* Wqbg   = (const float*)d_in[11];
    const float* gwih   = (const float*)d_in[12];
    const float* gwhh   = (const float*)d_in[13];
    const float* gbih   = (const float*)d_in[14];
    const float* gbhh   = (const float*)d_in[15];
    const float* bgwih  = (const float*)d_in[16];
    const float* bgwhh  = (const float*)d_in[17];
    const float* bgbih  = (const float*)d_in[18];
    const float* bgbhh  = (const float*)d_in[19];
    const float* rlng   = (const float*)d_in[20];
    const float* rlnb   = (const float*)d_in[21];
    const float* rw1    = (const float*)d_in[22];
    const float* rb1    = (const float*)d_in[23];
    const float* rw2    = (const float*)d_in[24];
    const float* rb2    = (const float*)d_in[25];
    const float* bglng  = (const float*)d_in[26];
    const float* bglnb  = (const float*)d_in[27];
    const float* bgw1   = (const float*)d_in[28];
    const float* bgb1   = (const float*)d_in[29];
    const float* bgw2   = (const float*)d_in[30];
    const float* bgb2   = (const float*)d_in[31];

    float* out       = (float*)d_out;
    float* out_attn  = out + SLOTS_*D_;   // slots first, then attn

    const int smem_lnkv = (128*128 + 64*128) * (int)sizeof(float);  // 98304 B
    cudaFuncSetAttribute(ln_kv_kernel,
                         cudaFuncAttributeMaxDynamicSharedMemorySize, smem_lnkv);

    ln_kv_kernel<<<296, 256, smem_lnkv>>>(feat, nfg, nfb, Wk, Wv);

    void* args[] = {
        (void*)&slot,
        (void*)&qg,   (void*)&qb,   (void*)&Wq,
        (void*)&qbgg, (void*)&qbgb, (void*)&Wqbg,
        (void*)&gwih, (void*)&gwhh, (void*)&gbih, (void*)&gbhh,
        (void*)&bgwih, (void*)&bgwhh, (void*)&bgbih, (void*)&bgbhh,
        (void*)&rlng, (void*)&rlnb, (void*)&rw1, (void*)&rb1,
        (void*)&rw2,  (void*)&rb2,
        (void*)&bglng, (void*)&bglnb, (void*)&bgw1, (void*)&bgb1,
        (void*)&bgw2,  (void*)&bgb2,
        (void*)&out, (void*)&out_attn
    };
    cudaLaunchCooperativeKernel((const void*)fused_iter_kernel,
                                dim3(512), dim3(256), args, 0, (cudaStream_t)0);
}